// round 5
// baseline (speedup 1.0000x reference)
#include <cuda_runtime.h>
#include <cuda_bf16.h>
#include <math.h>
#include <stdint.h>

#define B_   8
#define T_   4096
#define BT   (B_*T_)          // 32768 rows
#define DM   512
#define NH   8
#define HD   64

#define PADH  40                       // smem row stride in halves
#define TILEB (128*PADH*2)             // 10240 bytes per tile
#define STAGEB (4*TILEB)               // 40960 bytes per stage
#define SMEMB  (2*STAGEB)              // 81920 bytes total

// ---------------- scratch (static device globals; no allocation) ------------
__device__ float g_Q   [(size_t)BT * DM];      // Q fp32 (raw, roped in attn)
__device__ float g_KV  [(size_t)BT * 1024];    // kv raw fp32
__device__ float g_Ctx [B_*NH*HD*HD];
__device__ float g_Ksum[B_*NH*HD];
__device__ float g_RopC[T_*32];
__device__ float g_RopS[T_*32];

__device__ __nv_bfloat16 g_Xhi[(size_t)BT*DM],  g_Xlo[(size_t)BT*DM];
__device__ __nv_bfloat16 g_Chi[(size_t)BT*128], g_Clo[(size_t)BT*128];
__device__ __nv_bfloat16 g_AtH[(size_t)BT*DM],  g_AtL[(size_t)BT*DM];
__device__ __nv_bfloat16 g_WqH[512*512],  g_WqL[512*512];
__device__ __nv_bfloat16 g_WdH[128*512],  g_WdL[128*512];
__device__ __nv_bfloat16 g_WuH[1024*128], g_WuL[1024*128];
__device__ __nv_bfloat16 g_WoH[512*512],  g_WoL[512*512];

// ---------------- helpers ---------------------------------------------------
__device__ __forceinline__ uint32_t smem_u32(const void* p) {
    uint32_t a;
    asm("{ .reg .u64 t; cvta.to.shared.u64 t, %1; cvt.u32.u64 %0, t; }"
        : "=r"(a) : "l"(p));
    return a;
}
__device__ __forceinline__ void cpasync16(uint32_t s, const void* g) {
    asm volatile("cp.async.ca.shared.global [%0], [%1], 16;" :: "r"(s), "l"(g));
}
__device__ __forceinline__ void mma16816(float* d, const uint32_t* a, const uint32_t* b)
{
    asm volatile(
        "mma.sync.aligned.m16n8k16.row.col.f32.bf16.bf16.f32 "
        "{%0,%1,%2,%3}, {%4,%5,%6,%7}, {%8,%9}, {%0,%1,%2,%3};"
        : "+f"(d[0]), "+f"(d[1]), "+f"(d[2]), "+f"(d[3])
        : "r"(a[0]), "r"(a[1]), "r"(a[2]), "r"(a[3]), "r"(b[0]), "r"(b[1]));
}
__device__ __forceinline__ uint32_t pack_bf2(__nv_bfloat16 a, __nv_bfloat16 b)
{
    __nv_bfloat162 p; p.x = a; p.y = b;
    return *(uint32_t*)&p;
}

// ========== bf16 split-3 GEMM, cp.async double-buffered =====================
// D = Ahi@Bhi^T + Alo@Bhi^T + Ahi@Blo^T + bias.  A[*,K], B[N,K] bf16 row-major.
// 128x128 tile, BK=32, 256 threads (8 warps 2x4), warp tile 64x32.
__global__ __launch_bounds__(256, 2) void bgemm3(
    const __nv_bfloat16* __restrict__ Ahi, const __nv_bfloat16* __restrict__ Alo,
    const __nv_bfloat16* __restrict__ Bhi, const __nv_bfloat16* __restrict__ Blo,
    const float* __restrict__ bias,
    float* __restrict__ outF,
    __nv_bfloat16* __restrict__ outHi, __nv_bfloat16* __restrict__ outLo,
    int N, int K)
{
    extern __shared__ char smem[];
    const uint32_t sb = smem_u32(smem);

    const int tid  = threadIdx.x;
    const int lane = tid & 31;
    const int wid  = tid >> 5;
    const int wm   = (wid >> 2) * 64;
    const int wn   = (wid & 3) * 32;
    const int g    = lane >> 2;
    const int t2   = (lane & 3) * 2;
    const int m0   = blockIdx.y * 128;
    const int n0   = blockIdx.x * 128;

    const int lrow = tid >> 1;           // 0..127
    const int lc16 = (tid & 1) * 2;      // 16B-seg base (0 or 2)

    const __nv_bfloat16* gA0 = Ahi + (size_t)(m0 + lrow) * K + lc16 * 8;
    const __nv_bfloat16* gA1 = Alo + (size_t)(m0 + lrow) * K + lc16 * 8;
    const __nv_bfloat16* gB0 = Bhi + (size_t)(n0 + lrow) * K + lc16 * 8;
    const __nv_bfloat16* gB1 = Blo + (size_t)(n0 + lrow) * K + lc16 * 8;
    const uint32_t sdst = sb + lrow * (PADH*2) + lc16 * 16;

    const int nch = K >> 5;

    auto issue = [&](int ch, int st) {
        const uint32_t s0 = sdst + st * STAGEB;
        const int ko = ch * 32;
        cpasync16(s0,                 gA0 + ko);
        cpasync16(s0 + 16,            gA0 + ko + 8);
        cpasync16(s0 + TILEB,         gA1 + ko);
        cpasync16(s0 + TILEB + 16,    gA1 + ko + 8);
        cpasync16(s0 + 2*TILEB,      gB0 + ko);
        cpasync16(s0 + 2*TILEB + 16, gB0 + ko + 8);
        cpasync16(s0 + 3*TILEB,      gB1 + ko);
        cpasync16(s0 + 3*TILEB + 16, gB1 + ko + 8);
        asm volatile("cp.async.commit_group;" ::: "memory");
    };

    float acc[4][4][4];
    #pragma unroll
    for (int mt = 0; mt < 4; ++mt)
        #pragma unroll
        for (int nt = 0; nt < 4; ++nt)
            #pragma unroll
            for (int i = 0; i < 4; ++i) acc[mt][nt][i] = 0.f;

    issue(0, 0);
    for (int ch = 0; ch < nch; ++ch) {
        const int st = ch & 1;
        if (ch + 1 < nch) {
            issue(ch + 1, st ^ 1);
            asm volatile("cp.async.wait_group 1;" ::: "memory");
        } else {
            asm volatile("cp.async.wait_group 0;" ::: "memory");
        }
        __syncthreads();

        const __nv_bfloat16* sAhi = (const __nv_bfloat16*)(smem + st * STAGEB);
        const __nv_bfloat16* sAlo = sAhi + 128*PADH;
        const __nv_bfloat16* sBhi = sAlo + 128*PADH;
        const __nv_bfloat16* sBlo = sBhi + 128*PADH;

        #pragma unroll
        for (int ks = 0; ks < 2; ++ks) {
            const int k0 = ks * 16;
            uint32_t ah[4][4], al[4][4];
            #pragma unroll
            for (int mt = 0; mt < 4; ++mt) {
                int base = (wm + mt * 16 + g) * PADH + k0 + t2;
                ah[mt][0] = *(const uint32_t*)&sAhi[base];
                ah[mt][1] = *(const uint32_t*)&sAhi[base + 8 * PADH];
                ah[mt][2] = *(const uint32_t*)&sAhi[base + 8];
                ah[mt][3] = *(const uint32_t*)&sAhi[base + 8 * PADH + 8];
                al[mt][0] = *(const uint32_t*)&sAlo[base];
                al[mt][1] = *(const uint32_t*)&sAlo[base + 8 * PADH];
                al[mt][2] = *(const uint32_t*)&sAlo[base + 8];
                al[mt][3] = *(const uint32_t*)&sAlo[base + 8 * PADH + 8];
            }
            #pragma unroll
            for (int nt = 0; nt < 4; ++nt) {
                int nb = (wn + nt * 8 + g) * PADH + k0 + t2;
                uint32_t bh[2], bl[2];
                bh[0] = *(const uint32_t*)&sBhi[nb];
                bh[1] = *(const uint32_t*)&sBhi[nb + 8];
                bl[0] = *(const uint32_t*)&sBlo[nb];
                bl[1] = *(const uint32_t*)&sBlo[nb + 8];
                #pragma unroll
                for (int mt = 0; mt < 4; ++mt) {
                    mma16816(acc[mt][nt], ah[mt], bh);
                    mma16816(acc[mt][nt], al[mt], bh);
                    mma16816(acc[mt][nt], ah[mt], bl);
                }
            }
        }
        __syncthreads();
    }

    // epilogue
    #pragma unroll
    for (int mt = 0; mt < 4; ++mt) {
        int row = m0 + wm + mt * 16 + g;
        #pragma unroll
        for (int nt = 0; nt < 4; ++nt) {
            int col = n0 + wn + nt * 8 + t2;
            float b0 = bias[col], b1 = bias[col + 1];
            float v00 = acc[mt][nt][0] + b0, v01 = acc[mt][nt][1] + b1;
            float v10 = acc[mt][nt][2] + b0, v11 = acc[mt][nt][3] + b1;
            if (outF) {
                *(float2*)(outF + (size_t)row * N + col)       = make_float2(v00, v01);
                *(float2*)(outF + (size_t)(row + 8) * N + col) = make_float2(v10, v11);
            }
            if (outHi) {
                __nv_bfloat16 h00 = __float2bfloat16_rn(v00);
                __nv_bfloat16 h01 = __float2bfloat16_rn(v01);
                __nv_bfloat16 h10 = __float2bfloat16_rn(v10);
                __nv_bfloat16 h11 = __float2bfloat16_rn(v11);
                *(uint32_t*)(outHi + (size_t)row * N + col)       = pack_bf2(h00, h01);
                *(uint32_t*)(outHi + (size_t)(row + 8) * N + col) = pack_bf2(h10, h11);
                *(uint32_t*)(outLo + (size_t)row * N + col) = pack_bf2(
                    __float2bfloat16_rn(v00 - __bfloat162float(h00)),
                    __float2bfloat16_rn(v01 - __bfloat162float(h01)));
                *(uint32_t*)(outLo + (size_t)(row + 8) * N + col) = pack_bf2(
                    __float2bfloat16_rn(v10 - __bfloat162float(h10)),
                    __float2bfloat16_rn(v11 - __bfloat162float(h11)));
            }
        }
    }
}

// ---------------- split fp32 -> bf16 hi/lo (no transpose) -------------------
__global__ __launch_bounds__(256) void split_rows(
    const float* __restrict__ X, __nv_bfloat16* __restrict__ Hi,
    __nv_bfloat16* __restrict__ Lo)
{
    size_t e0 = ((size_t)blockIdx.x * 256 + threadIdx.x) * 4;
    float4 v = *(const float4*)(X + e0);
    __nv_bfloat16 h0 = __float2bfloat16_rn(v.x), h1 = __float2bfloat16_rn(v.y);
    __nv_bfloat16 h2 = __float2bfloat16_rn(v.z), h3 = __float2bfloat16_rn(v.w);
    uint2 hh = make_uint2(pack_bf2(h0, h1), pack_bf2(h2, h3));
    uint2 ll = make_uint2(
        pack_bf2(__float2bfloat16_rn(v.x - __bfloat162float(h0)),
                 __float2bfloat16_rn(v.y - __bfloat162float(h1))),
        pack_bf2(__float2bfloat16_rn(v.z - __bfloat162float(h2)),
                 __float2bfloat16_rn(v.w - __bfloat162float(h3))));
    *(uint2*)(Hi + e0) = hh;
    *(uint2*)(Lo + e0) = ll;
}

// ------- weight transpose + split: W[K,N] -> WtHi/WtLo[N,K] bf16 ------------
__global__ __launch_bounds__(256) void split_weightT(
    const float* __restrict__ W, __nv_bfloat16* __restrict__ Whi,
    __nv_bfloat16* __restrict__ Wlo, int K, int N)
{
    __shared__ float t[32][33];
    int kb = blockIdx.y * 32, nb = blockIdx.x * 32;
    int x = threadIdx.x & 31, y = threadIdx.x >> 5;
    #pragma unroll
    for (int i = 0; i < 32; i += 8)
        t[y + i][x] = W[(size_t)(kb + y + i) * N + nb + x];
    __syncthreads();
    #pragma unroll
    for (int i = 0; i < 32; i += 8) {
        float v = t[x][y + i];
        __nv_bfloat16 h = __float2bfloat16_rn(v);
        Whi[(size_t)(nb + y + i) * K + kb + x] = h;
        Wlo[(size_t)(nb + y + i) * K + kb + x] =
            __float2bfloat16_rn(v - __bfloat162float(h));
    }
}

// ---------------- rope cos/sin table ----------------------------------------
__global__ __launch_bounds__(128) void rope_table()
{
    int idx = blockIdx.x * 128 + threadIdx.x;    // T_*32
    int t = idx >> 5, j = idx & 31;
    const float LOG2_1E4 = 13.2877123795494f;
    float freq = exp2f(-(float)j * (LOG2_1E4 / 32.f));
    float s, c;
    sincosf((float)t * freq, &s, &c);
    g_RopC[idx] = c;
    g_RopS[idx] = s;
}

__device__ __forceinline__ float elu1(float x) {
    return (x > 0.f) ? (x + 1.f) : expf(x);
}

// ------- context[b,h] = sum_t rope_elu(k)(t) outer v(t); ksum too -----------
__global__ __launch_bounds__(256) void context_kernel()
{
    const int p  = blockIdx.y;
    const int b  = p >> 3;
    const int h  = p & 7;
    const int t0 = blockIdx.x * 256;

    __shared__ float Ks[32][64];
    __shared__ float Vs[32][64];

    const int tid = threadIdx.x;
    const int tx  = tid & 15;
    const int ty  = tid >> 4;
    const int kr_ = tid >> 3;          // 0..31 (K pair row)
    const int kc4 = (tid & 7) * 4;     // 0..28 (c in [0,32))

    float acc[4][4];
    #pragma unroll
    for (int i = 0; i < 4; ++i)
        #pragma unroll
        for (int j = 0; j < 4; ++j) acc[i][j] = 0.f;
    float ksm[4] = {0.f, 0.f, 0.f, 0.f};

    for (int tt = 0; tt < 256; tt += 32) {
        // K with rope + elu+1: one (c, c+32) float4 pair per thread
        {
            int t = t0 + tt + kr_;
            size_t base = (size_t)(b * T_ + t) * 1024 + h * 128;
            float4 x1 = *(const float4*)(g_KV + base + kc4);
            float4 x2 = *(const float4*)(g_KV + base + 32 + kc4);
            float4 cs = *(const float4*)(g_RopC + t * 32 + kc4);
            float4 sn = *(const float4*)(g_RopS + t * 32 + kc4);
            Ks[kr_][kc4+0]    = elu1(x1.x*cs.x - x2.x*sn.x);
            Ks[kr_][kc4+1]    = elu1(x1.y*cs.y - x2.y*sn.y);
            Ks[kr_][kc4+2]    = elu1(x1.z*cs.z - x2.z*sn.z);
            Ks[kr_][kc4+3]    = elu1(x1.w*cs.w - x2.w*sn.w);
            Ks[kr_][kc4+32]   = elu1(x1.x*sn.x + x2.x*cs.x);
            Ks[kr_][kc4+33]   = elu1(x1.y*sn.y + x2.y*cs.y);
            Ks[kr_][kc4+34]   = elu1(x1.z*sn.z + x2.z*cs.z);
            Ks[kr_][kc4+35]   = elu1(x1.w*sn.w + x2.w*cs.w);
        }
        // V plain: 2 float4 per thread
        #pragma unroll
        for (int ii = 0; ii < 2; ++ii) {
            int i = tid + ii * 256;
            int r = i >> 4;
            int c = (i & 15) * 4;
            size_t base = (size_t)(b * T_ + t0 + tt + r) * 1024 + h * 128;
            *(float4*)&Vs[r][c] = *(const float4*)(g_KV + base + 64 + c);
        }
        __syncthreads();
        #pragma unroll 8
        for (int t = 0; t < 32; ++t) {
            float kr[4], vr[4];
            *(float4*)kr = *(const float4*)&Ks[t][ty*4];
            *(float4*)vr = *(const float4*)&Vs[t][tx*4];
            #pragma unroll
            for (int i = 0; i < 4; ++i)
                #pragma unroll
                for (int j = 0; j < 4; ++j)
                    acc[i][j] = fmaf(kr[i], vr[j], acc[i][j]);
            if (tx == 0) {
                #pragma unroll
                for (int i = 0; i < 4; ++i) ksm[i] += kr[i];
            }
        }
        __syncthreads();
    }

    float* ctx = g_Ctx + (size_t)p * HD * HD;
    #pragma unroll
    for (int i = 0; i < 4; ++i)
        #pragma unroll
        for (int j = 0; j < 4; ++j)
            atomicAdd(&ctx[(ty*4 + i) * HD + tx*4 + j], acc[i][j]);
    if (tx == 0) {
        #pragma unroll
        for (int i = 0; i < 4; ++i)
            atomicAdd(&g_Ksum[p * HD + ty*4 + i], ksm[i]);
    }
}

// ------- attn: out = (rope_elu(q) @ ctx) * z ; writes bf16 hi/lo ------------
__global__ __launch_bounds__(256) void attn_kernel()
{
    const int h  = blockIdx.y;
    const int r0 = blockIdx.x * 64;
    const int b  = r0 >> 12;
    const int p  = b * NH + h;

    __shared__ float Cs[64][64];
    __shared__ float Qs[64][65];
    __shared__ float ks[64];
    __shared__ float zs[64];

    const int tid = threadIdx.x;

    for (int i = tid; i < 64*64; i += 256)
        Cs[i >> 6][i & 63] = g_Ctx[(size_t)p * HD * HD + i];
    if (tid < 64) ks[tid] = g_Ksum[p * HD + tid];

    // Q load with rope + elu+1: pairs (c, c+32), 2 pairs per thread
    #pragma unroll
    for (int ii = 0; ii < 2; ++ii) {
        int i = tid + ii * 256;          // 0..511
        int r = i >> 3;                  // 0..63
        int c4 = (i & 7) * 4;            // 0..28
        int t = (r0 + r) & (T_ - 1);
        size_t base = (size_t)(r0 + r) * DM + h * HD;
        float4 x1 = *(const float4*)(g_Q + base + c4);
        float4 x2 = *(const float4*)(g_Q + base + 32 + c4);
        float4 cs = *(const float4*)(g_RopC + t * 32 + c4);
        float4 sn = *(const float4*)(g_RopS + t * 32 + c4);
        Qs[r][c4+0]  = elu1(x1.x*cs.x - x2.x*sn.x);
        Qs[r][c4+1]  = elu1(x1.y*cs.y - x2.y*sn.y);
        Qs[r][c4+2]  = elu1(x1.z*cs.z - x2.z*sn.z);
        Qs[r][c4+3]  = elu1(x1.w*cs.w - x2.w*sn.w);
        Qs[r][c4+32] = elu1(x1.x*sn.x + x2.x*cs.x);
        Qs[r][c4+33] = elu1(x1.y*sn.y + x2.y*cs.y);
        Qs[r][c4+34] = elu1(x1.z*sn.z + x2.z*cs.z);
        Qs[r][c4+35] = elu1(x1.w*sn.w + x2.w*cs.w);
    }
    __syncthreads();

    if (tid < 64) {
        float dsum = 0.f;
        #pragma unroll
        for (int d = 0; d < 64; ++d) dsum += Qs[tid][d] * ks[d];
        zs[tid] = 1.f / (dsum + 1e-6f);
    }
    __syncthreads();

    const int tx = tid & 15;
    const int ty = tid >> 4;
    float acc[4][4];
    #pragma unroll
    for (int i = 0; i < 4; ++i)
        #pragma unroll
        for (int j = 0; j < 4; ++j) acc[i][j] = 0.f;

    #pragma unroll
    for (int d = 0; d < 64; ++d) {
        float4 cv = *(const float4*)&Cs[d][tx*4];
        float q0 = Qs[ty*4+0][d];
        float q1 = Qs[ty*4+1][d];
        float q2 = Qs[ty*4+2][d];
        float q3 = Qs[ty*4+3][d];
        acc[0][0] = fmaf(q0, cv.x, acc[0][0]); acc[0][1] = fmaf(q0, cv.y, acc[0][1]);
        acc[0][2] = fmaf(q0, cv.z, acc[0][2]); acc[0][3] = fmaf(q0, cv.w, acc[0][3]);
        acc[1][0] = fmaf(q1, cv.x, acc[1][0]); acc[1][1] = fmaf(q1, cv.y, acc[1][1]);
        acc[1][2] = fmaf(q1, cv.z, acc[1][2]); acc[1][3] = fmaf(q1, cv.w, acc[1][3]);
        acc[2][0] = fmaf(q2, cv.x, acc[2][0]); acc[2][1] = fmaf(q2, cv.y, acc[2][1]);
        acc[2][2] = fmaf(q2, cv.z, acc[2][2]); acc[2][3] = fmaf(q2, cv.w, acc[2][3]);
        acc[3][0] = fmaf(q3, cv.x, acc[3][0]); acc[3][1] = fmaf(q3, cv.y, acc[3][1]);
        acc[3][2] = fmaf(q3, cv.z, acc[3][2]); acc[3][3] = fmaf(q3, cv.w, acc[3][3]);
    }

    #pragma unroll
    for (int i = 0; i < 4; ++i) {
        int r = ty*4 + i;
        float z = zs[r];
        float v0 = acc[i][0]*z, v1 = acc[i][1]*z, v2 = acc[i][2]*z, v3 = acc[i][3]*z;
        size_t off = (size_t)(r0 + r) * DM + h * HD + tx*4;
        __nv_bfloat16 h0 = __float2bfloat16_rn(v0), h1 = __float2bfloat16_rn(v1);
        __nv_bfloat16 h2 = __float2bfloat16_rn(v2), h3 = __float2bfloat16_rn(v3);
        *(uint32_t*)(g_AtH + off)     = pack_bf2(h0, h1);
        *(uint32_t*)(g_AtH + off + 2) = pack_bf2(h2, h3);
        *(uint32_t*)(g_AtL + off) = pack_bf2(
            __float2bfloat16_rn(v0 - __bfloat162float(h0)),
            __float2bfloat16_rn(v1 - __bfloat162float(h1)));
        *(uint32_t*)(g_AtL + off + 2) = pack_bf2(
            __float2bfloat16_rn(v2 - __bfloat162float(h2)),
            __float2bfloat16_rn(v3 - __bfloat162float(h3)));
    }
}

// ---------------------------------------------------------------------------
extern "C" void kernel_launch(void* const* d_in, const int* in_sizes, int n_in,
                              void* d_out, int out_size)
{
    const float* x  = (const float*)d_in[0];
    const float* Wq = (const float*)d_in[1];
    const float* bq = (const float*)d_in[2];
    const float* Wd = (const float*)d_in[3];
    const float* bd = (const float*)d_in[4];
    const float* Wu = (const float*)d_in[5];
    const float* bu = (const float*)d_in[6];
    const float* Wo = (const float*)d_in[7];
    const float* bo = (const float*)d_in[8];
    float* out = (float*)d_out;

    float *pQ, *pKV, *pCtx, *pKsum;
    __nv_bfloat16 *pXh, *pXl, *pCh, *pCl, *pAh, *pAl;
    __nv_bfloat16 *pWqH, *pWqL, *pWdH, *pWdL, *pWuH, *pWuL, *pWoH, *pWoL;
    cudaGetSymbolAddress((void**)&pQ,    g_Q);
    cudaGetSymbolAddress((void**)&pKV,   g_KV);
    cudaGetSymbolAddress((void**)&pCtx,  g_Ctx);
    cudaGetSymbolAddress((void**)&pKsum, g_Ksum);
    cudaGetSymbolAddress((void**)&pXh,   g_Xhi);
    cudaGetSymbolAddress((void**)&pXl,   g_Xlo);
    cudaGetSymbolAddress((void**)&pCh,   g_Chi);
    cudaGetSymbolAddress((void**)&pCl,   g_Clo);
    cudaGetSymbolAddress((void**)&pAh,   g_AtH);
    cudaGetSymbolAddress((void**)&pAl,   g_AtL);
    cudaGetSymbolAddress((void**)&pWqH,  g_WqH);
    cudaGetSymbolAddress((void**)&pWqL,  g_WqL);
    cudaGetSymbolAddress((void**)&pWdH,  g_WdH);
    cudaGetSymbolAddress((void**)&pWdL,  g_WdL);
    cudaGetSymbolAddress((void**)&pWuH,  g_WuH);
    cudaGetSymbolAddress((void**)&pWuL,  g_WuL);
    cudaGetSymbolAddress((void**)&pWoH,  g_WoH);
    cudaGetSymbolAddress((void**)&pWoL,  g_WoL);

    static bool attr_set = false;
    if (!attr_set) {
        cudaFuncSetAttribute(bgemm3, cudaFuncAttributeMaxDynamicSharedMemorySize, SMEMB);
        attr_set = true;
    }

    // weights: transpose + split
    split_weightT<<<dim3(512/32, 512/32), 256>>>(Wq, pWqH, pWqL, 512, 512);
    split_weightT<<<dim3(128/32, 512/32), 256>>>(Wd, pWdH, pWdL, 512, 128);
    split_weightT<<<dim3(1024/32, 128/32), 256>>>(Wu, pWuH, pWuL, 128, 1024);
    split_weightT<<<dim3(512/32, 512/32), 256>>>(Wo, pWoH, pWoL, 512, 512);
    // rope table
    rope_table<<<T_*32/128, 128>>>();
    // x split
    split_rows<<<(size_t)BT*512/4/256, 256>>>(x, pXh, pXl);

    // Q = x @ Wq + bq  (fp32 out)
    bgemm3<<<dim3(4, BT/128), 256, SMEMB>>>(pXh, pXl, pWqH, pWqL, bq,
                                            pQ, nullptr, nullptr, 512, 512);
    // C = x @ Wd + bd  (hi/lo out only)
    bgemm3<<<dim3(1, BT/128), 256, SMEMB>>>(pXh, pXl, pWdH, pWdL, bd,
                                            nullptr, pCh, pCl, 128, 512);
    // KV = C @ Wu + bu (fp32 out)
    bgemm3<<<dim3(8, BT/128), 256, SMEMB>>>(pCh, pCl, pWuH, pWuL, bu,
                                            pKV, nullptr, nullptr, 1024, 128);

    // context (rope+elu on K fused into load)
    cudaMemsetAsync(pCtx,  0, sizeof(float) * B_*NH*HD*HD);
    cudaMemsetAsync(pKsum, 0, sizeof(float) * B_*NH*HD);
    context_kernel<<<dim3(T_/256, B_*NH), 256>>>();

    // attn (rope+elu on Q fused; writes bf16 hi/lo)
    attn_kernel<<<dim3(BT/64, NH), 256>>>();

    // out = Attn @ Wo + bo (fp32 out)
    bgemm3<<<dim3(4, BT/128), 256, SMEMB>>>(pAh, pAl, pWoH, pWoL, bo,
                                            out, nullptr, nullptr, 512, 512);
}

// round 6
// speedup vs baseline: 1.5348x; 1.5348x over previous
#include <cuda_runtime.h>
#include <cuda_bf16.h>
#include <math.h>
#include <stdint.h>

#define B_   8
#define T_   4096
#define BT   (B_*T_)          // 32768 rows
#define DM   512
#define NH   8
#define HD   64

#define PADH 40               // smem row stride in halves (80B; conflict-free)

// ---------------- scratch (static device globals; no allocation) ------------
__device__ float g_Q   [(size_t)BT * DM];      // Q fp32 (raw; roped in attn)
__device__ float g_KV  [(size_t)BT * 1024];    // kv raw fp32 (K roped in context)
__device__ float g_Ctx [B_*NH*HD*HD];
__device__ float g_Ksum[B_*NH*HD];
__device__ float g_RopC[T_*32];
__device__ float g_RopS[T_*32];

__device__ __nv_bfloat16 g_Xhi[(size_t)BT*DM],  g_Xlo[(size_t)BT*DM];
__device__ __nv_bfloat16 g_Chi[(size_t)BT*128], g_Clo[(size_t)BT*128];
__device__ __nv_bfloat16 g_AtH[(size_t)BT*DM],  g_AtL[(size_t)BT*DM];
__device__ __nv_bfloat16 g_WqH[512*512],  g_WqL[512*512];
__device__ __nv_bfloat16 g_WdH[128*512],  g_WdL[128*512];
__device__ __nv_bfloat16 g_WuH[1024*128], g_WuL[1024*128];
__device__ __nv_bfloat16 g_WoH[512*512],  g_WoL[512*512];

// ---------------- helpers ---------------------------------------------------
__device__ __forceinline__ uint32_t smem_u32(const void* p) {
    uint32_t a;
    asm("{ .reg .u64 t; cvta.to.shared.u64 t, %1; cvt.u32.u64 %0, t; }"
        : "=r"(a) : "l"(p));
    return a;
}
__device__ __forceinline__ void mma16816(float* d, const uint32_t* a, const uint32_t* b)
{
    asm volatile(
        "mma.sync.aligned.m16n8k16.row.col.f32.bf16.bf16.f32 "
        "{%0,%1,%2,%3}, {%4,%5,%6,%7}, {%8,%9}, {%0,%1,%2,%3};"
        : "+f"(d[0]), "+f"(d[1]), "+f"(d[2]), "+f"(d[3])
        : "r"(a[0]), "r"(a[1]), "r"(a[2]), "r"(a[3]), "r"(b[0]), "r"(b[1]));
}
__device__ __forceinline__ void ldsm_x4(uint32_t* r, uint32_t addr) {
    asm volatile("ldmatrix.sync.aligned.m8n8.x4.shared.b16 {%0,%1,%2,%3}, [%4];"
        : "=r"(r[0]), "=r"(r[1]), "=r"(r[2]), "=r"(r[3]) : "r"(addr));
}
__device__ __forceinline__ void ldsm_x2(uint32_t* r, uint32_t addr) {
    asm volatile("ldmatrix.sync.aligned.m8n8.x2.shared.b16 {%0,%1}, [%2];"
        : "=r"(r[0]), "=r"(r[1]) : "r"(addr));
}
__device__ __forceinline__ uint32_t pack_bf2(__nv_bfloat16 a, __nv_bfloat16 b)
{
    __nv_bfloat162 p; p.x = a; p.y = b;
    return *(uint32_t*)&p;
}

// ========== bf16 split-3 GEMM (register prefetch + ldmatrix) ================
// D = Ahi@Bhi^T + Alo@Bhi^T + Ahi@Blo^T + bias.  A[*,K], B[N,K] bf16 row-major.
// 128x128 tile, BK=32, 256 threads (8 warps 2x4), warp tile 64x32.
__global__ __launch_bounds__(256) void bgemm3(
    const __nv_bfloat16* __restrict__ Ahi, const __nv_bfloat16* __restrict__ Alo,
    const __nv_bfloat16* __restrict__ Bhi, const __nv_bfloat16* __restrict__ Blo,
    const float* __restrict__ bias,
    float* __restrict__ outF,
    __nv_bfloat16* __restrict__ outHi, __nv_bfloat16* __restrict__ outLo,
    int N, int K)
{
    __shared__ __nv_bfloat16 sAhi[128*PADH];
    __shared__ __nv_bfloat16 sAlo[128*PADH];
    __shared__ __nv_bfloat16 sBhi[128*PADH];
    __shared__ __nv_bfloat16 sBlo[128*PADH];

    const int tid  = threadIdx.x;
    const int lane = tid & 31;
    const int wid  = tid >> 5;
    const int wm   = (wid >> 2) * 64;
    const int wn   = (wid & 3) * 32;
    const int g    = lane >> 2;
    const int t2   = (lane & 3) * 2;
    const int m0   = blockIdx.y * 128;
    const int n0   = blockIdx.x * 128;

    // loader: uint4 = 8 halves; rows lrow and lrow+64, segment lseg
    const int lrow = tid >> 2;           // 0..63
    const int lseg = tid & 3;            // 0..3 (16B seg within 64B row)

    const __nv_bfloat16* gA0 = Ahi + (size_t)(m0 + lrow) * K + lseg * 8;
    const __nv_bfloat16* gA1 = Alo + (size_t)(m0 + lrow) * K + lseg * 8;
    const __nv_bfloat16* gB0 = Bhi + (size_t)(n0 + lrow) * K + lseg * 8;
    const __nv_bfloat16* gB1 = Blo + (size_t)(n0 + lrow) * K + lseg * 8;
    const size_t rstep = (size_t)64 * K;   // +64 rows

    // ldmatrix per-lane address components
    const int a_row  = ((lane >> 3) & 1) * 8 + (lane & 7);
    const int a_col8 = (lane >> 4) * 8;
    const int b_row  = (lane & 7);
    const int b_col8 = ((lane >> 3) & 1) * 8;

    const uint32_t uAhi = smem_u32(sAhi);
    const uint32_t uAlo = smem_u32(sAlo);
    const uint32_t uBhi = smem_u32(sBhi);
    const uint32_t uBlo = smem_u32(sBlo);

    const uint32_t soff = (uint32_t)(lrow * (PADH*2) + lseg * 16);
    const uint32_t soff2 = soff + (uint32_t)(64 * PADH * 2);

    const int nch = K >> 5;

    uint4 pA0[2], pA1[2], pB0[2], pB1[2];
    pA0[0] = *(const uint4*)gA0; pA0[1] = *(const uint4*)(gA0 + rstep);
    pA1[0] = *(const uint4*)gA1; pA1[1] = *(const uint4*)(gA1 + rstep);
    pB0[0] = *(const uint4*)gB0; pB0[1] = *(const uint4*)(gB0 + rstep);
    pB1[0] = *(const uint4*)gB1; pB1[1] = *(const uint4*)(gB1 + rstep);

    float acc[4][4][4];
    #pragma unroll
    for (int mt = 0; mt < 4; ++mt)
        #pragma unroll
        for (int nt = 0; nt < 4; ++nt)
            #pragma unroll
            for (int i = 0; i < 4; ++i) acc[mt][nt][i] = 0.f;

    for (int ch = 0; ch < nch; ++ch) {
        *(uint4*)((char*)sAhi + soff)  = pA0[0];
        *(uint4*)((char*)sAhi + soff2) = pA0[1];
        *(uint4*)((char*)sAlo + soff)  = pA1[0];
        *(uint4*)((char*)sAlo + soff2) = pA1[1];
        *(uint4*)((char*)sBhi + soff)  = pB0[0];
        *(uint4*)((char*)sBhi + soff2) = pB0[1];
        *(uint4*)((char*)sBlo + soff)  = pB1[0];
        *(uint4*)((char*)sBlo + soff2) = pB1[1];
        __syncthreads();

        if (ch + 1 < nch) {
            const int ko = (ch + 1) * 32;
            pA0[0] = *(const uint4*)(gA0 + ko); pA0[1] = *(const uint4*)(gA0 + rstep + ko);
            pA1[0] = *(const uint4*)(gA1 + ko); pA1[1] = *(const uint4*)(gA1 + rstep + ko);
            pB0[0] = *(const uint4*)(gB0 + ko); pB0[1] = *(const uint4*)(gB0 + rstep + ko);
            pB1[0] = *(const uint4*)(gB1 + ko); pB1[1] = *(const uint4*)(gB1 + rstep + ko);
        }

        #pragma unroll
        for (int ks = 0; ks < 2; ++ks) {
            const int k0 = ks * 16;
            uint32_t ah[4][4], al[4][4];
            #pragma unroll
            for (int mt = 0; mt < 4; ++mt) {
                uint32_t off = (uint32_t)(((wm + mt*16 + a_row) * PADH + k0 + a_col8) * 2);
                ldsm_x4(ah[mt], uAhi + off);
                ldsm_x4(al[mt], uAlo + off);
            }
            #pragma unroll
            for (int nt = 0; nt < 4; ++nt) {
                uint32_t boff = (uint32_t)(((wn + nt*8 + b_row) * PADH + k0 + b_col8) * 2);
                uint32_t bh[2], bl[2];
                ldsm_x2(bh, uBhi + boff);
                ldsm_x2(bl, uBlo + boff);
                #pragma unroll
                for (int mt = 0; mt < 4; ++mt) {
                    mma16816(acc[mt][nt], ah[mt], bh);
                    mma16816(acc[mt][nt], al[mt], bh);
                    mma16816(acc[mt][nt], ah[mt], bl);
                }
            }
        }
        __syncthreads();
    }

    // epilogue: bias add, fp32 and/or bf16 hi/lo outputs
    #pragma unroll
    for (int mt = 0; mt < 4; ++mt) {
        int row = m0 + wm + mt * 16 + g;
        #pragma unroll
        for (int nt = 0; nt < 4; ++nt) {
            int col = n0 + wn + nt * 8 + t2;
            float b0 = bias[col], b1 = bias[col + 1];
            float v00 = acc[mt][nt][0] + b0, v01 = acc[mt][nt][1] + b1;
            float v10 = acc[mt][nt][2] + b0, v11 = acc[mt][nt][3] + b1;
            if (outF) {
                *(float2*)(outF + (size_t)row * N + col)       = make_float2(v00, v01);
                *(float2*)(outF + (size_t)(row + 8) * N + col) = make_float2(v10, v11);
            }
            if (outHi) {
                __nv_bfloat16 h00 = __float2bfloat16_rn(v00);
                __nv_bfloat16 h01 = __float2bfloat16_rn(v01);
                __nv_bfloat16 h10 = __float2bfloat16_rn(v10);
                __nv_bfloat16 h11 = __float2bfloat16_rn(v11);
                *(uint32_t*)(outHi + (size_t)row * N + col)       = pack_bf2(h00, h01);
                *(uint32_t*)(outHi + (size_t)(row + 8) * N + col) = pack_bf2(h10, h11);
                *(uint32_t*)(outLo + (size_t)row * N + col) = pack_bf2(
                    __float2bfloat16_rn(v00 - __bfloat162float(h00)),
                    __float2bfloat16_rn(v01 - __bfloat162float(h01)));
                *(uint32_t*)(outLo + (size_t)(row + 8) * N + col) = pack_bf2(
                    __float2bfloat16_rn(v10 - __bfloat162float(h10)),
                    __float2bfloat16_rn(v11 - __bfloat162float(h11)));
            }
        }
    }
}

// ---------------- split fp32 -> bf16 hi/lo (no transpose) -------------------
__global__ __launch_bounds__(256) void split_rows(
    const float* __restrict__ X, __nv_bfloat16* __restrict__ Hi,
    __nv_bfloat16* __restrict__ Lo)
{
    size_t e0 = ((size_t)blockIdx.x * 256 + threadIdx.x) * 4;
    float4 v = *(const float4*)(X + e0);
    __nv_bfloat16 h0 = __float2bfloat16_rn(v.x), h1 = __float2bfloat16_rn(v.y);
    __nv_bfloat16 h2 = __float2bfloat16_rn(v.z), h3 = __float2bfloat16_rn(v.w);
    uint2 hh = make_uint2(pack_bf2(h0, h1), pack_bf2(h2, h3));
    uint2 ll = make_uint2(
        pack_bf2(__float2bfloat16_rn(v.x - __bfloat162float(h0)),
                 __float2bfloat16_rn(v.y - __bfloat162float(h1))),
        pack_bf2(__float2bfloat16_rn(v.z - __bfloat162float(h2)),
                 __float2bfloat16_rn(v.w - __bfloat162float(h3))));
    *(uint2*)(Hi + e0) = hh;
    *(uint2*)(Lo + e0) = ll;
}

// ------- weight transpose + split: W[K,N] -> WtHi/WtLo[N,K] bf16 ------------
__global__ __launch_bounds__(256) void split_weightT(
    const float* __restrict__ W, __nv_bfloat16* __restrict__ Whi,
    __nv_bfloat16* __restrict__ Wlo, int K, int N)
{
    __shared__ float t[32][33];
    int kb = blockIdx.y * 32, nb = blockIdx.x * 32;
    int x = threadIdx.x & 31, y = threadIdx.x >> 5;
    #pragma unroll
    for (int i = 0; i < 32; i += 8)
        t[y + i][x] = W[(size_t)(kb + y + i) * N + nb + x];
    __syncthreads();
    #pragma unroll
    for (int i = 0; i < 32; i += 8) {
        float v = t[x][y + i];
        __nv_bfloat16 h = __float2bfloat16_rn(v);
        Whi[(size_t)(nb + y + i) * K + kb + x] = h;
        Wlo[(size_t)(nb + y + i) * K + kb + x] =
            __float2bfloat16_rn(v - __bfloat162float(h));
    }
}

// ---------------- rope cos/sin table ----------------------------------------
__global__ __launch_bounds__(128) void rope_table()
{
    int idx = blockIdx.x * 128 + threadIdx.x;    // T_*32
    int t = idx >> 5, j = idx & 31;
    const float LOG2_1E4 = 13.2877123795494f;
    float freq = exp2f(-(float)j * (LOG2_1E4 / 32.f));
    float s, c;
    sincosf((float)t * freq, &s, &c);
    g_RopC[idx] = c;
    g_RopS[idx] = s;
}

__device__ __forceinline__ float elu1(float x) {
    return (x > 0.f) ? (x + 1.f) : expf(x);
}

// ------- context[b,h] = sum_t rope_elu(k)(t) outer v(t); ksum too -----------
__global__ __launch_bounds__(256) void context_kernel()
{
    const int p  = blockIdx.y;
    const int b  = p >> 3;
    const int h  = p & 7;
    const int t0 = blockIdx.x * 256;

    __shared__ float Ks[32][64];
    __shared__ float Vs[32][64];

    const int tid = threadIdx.x;
    const int tx  = tid & 15;
    const int ty  = tid >> 4;
    const int kr_ = tid >> 3;          // 0..31
    const int kc4 = (tid & 7) * 4;     // 0..28

    float acc[4][4];
    #pragma unroll
    for (int i = 0; i < 4; ++i)
        #pragma unroll
        for (int j = 0; j < 4; ++j) acc[i][j] = 0.f;
    float ksm[4] = {0.f, 0.f, 0.f, 0.f};

    for (int tt = 0; tt < 256; tt += 32) {
        {
            int t = t0 + tt + kr_;
            size_t base = (size_t)(b * T_ + t) * 1024 + h * 128;
            float4 x1 = *(const float4*)(g_KV + base + kc4);
            float4 x2 = *(const float4*)(g_KV + base + 32 + kc4);
            float4 cs = *(const float4*)(g_RopC + t * 32 + kc4);
            float4 sn = *(const float4*)(g_RopS + t * 32 + kc4);
            Ks[kr_][kc4+0]    = elu1(x1.x*cs.x - x2.x*sn.x);
            Ks[kr_][kc4+1]    = elu1(x1.y*cs.y - x2.y*sn.y);
            Ks[kr_][kc4+2]    = elu1(x1.z*cs.z - x2.z*sn.z);
            Ks[kr_][kc4+3]    = elu1(x1.w*cs.w - x2.w*sn.w);
            Ks[kr_][kc4+32]   = elu1(x1.x*sn.x + x2.x*cs.x);
            Ks[kr_][kc4+33]   = elu1(x1.y*sn.y + x2.y*cs.y);
            Ks[kr_][kc4+34]   = elu1(x1.z*sn.z + x2.z*cs.z);
            Ks[kr_][kc4+35]   = elu1(x1.w*sn.w + x2.w*cs.w);
        }
        #pragma unroll
        for (int ii = 0; ii < 2; ++ii) {
            int i = tid + ii * 256;
            int r = i >> 4;
            int c = (i & 15) * 4;
            size_t base = (size_t)(b * T_ + t0 + tt + r) * 1024 + h * 128;
            *(float4*)&Vs[r][c] = *(const float4*)(g_KV + base + 64 + c);
        }
        __syncthreads();
        #pragma unroll 8
        for (int t = 0; t < 32; ++t) {
            float kr[4], vr[4];
            *(float4*)kr = *(const float4*)&Ks[t][ty*4];
            *(float4*)vr = *(const float4*)&Vs[t][tx*4];
            #pragma unroll
            for (int i = 0; i < 4; ++i)
                #pragma unroll
                for (int j = 0; j < 4; ++j)
                    acc[i][j] = fmaf(kr[i], vr[j], acc[i][j]);
            if (tx == 0) {
                #pragma unroll
                for (int i = 0; i < 4; ++i) ksm[i] += kr[i];
            }
        }
        __syncthreads();
    }

    float* ctx = g_Ctx + (size_t)p * HD * HD;
    #pragma unroll
    for (int i = 0; i < 4; ++i)
        #pragma unroll
        for (int j = 0; j < 4; ++j)
            atomicAdd(&ctx[(ty*4 + i) * HD + tx*4 + j], acc[i][j]);
    if (tx == 0) {
        #pragma unroll
        for (int i = 0; i < 4; ++i)
            atomicAdd(&g_Ksum[p * HD + ty*4 + i], ksm[i]);
    }
}

// ------- attn: out = (rope_elu(q) @ ctx) * z ; writes bf16 hi/lo ------------
__global__ __launch_bounds__(256) void attn_kernel()
{
    const int h  = blockIdx.y;
    const int r0 = blockIdx.x * 64;
    const int b  = r0 >> 12;
    const int p  = b * NH + h;

    __shared__ float Cs[64][64];
    __shared__ float Qs[64][65];
    __shared__ float ks[64];
    __shared__ float zs[64];

    const int tid = threadIdx.x;

    for (int i = tid; i < 64*64; i += 256)
        Cs[i >> 6][i & 63] = g_Ctx[(size_t)p * HD * HD + i];
    if (tid < 64) ks[tid] = g_Ksum[p * HD + tid];

    #pragma unroll
    for (int ii = 0; ii < 2; ++ii) {
        int i = tid + ii * 256;
        int r = i >> 3;
        int c4 = (i & 7) * 4;
        int t = (r0 + r) & (T_ - 1);
        size_t base = (size_t)(r0 + r) * DM + h * HD;
        float4 x1 = *(const float4*)(g_Q + base + c4);
        float4 x2 = *(const float4*)(g_Q + base + 32 + c4);
        float4 cs = *(const float4*)(g_RopC + t * 32 + c4);
        float4 sn = *(const float4*)(g_RopS + t * 32 + c4);
        Qs[r][c4+0]  = elu1(x1.x*cs.x - x2.x*sn.x);
        Qs[r][c4+1]  = elu1(x1.y*cs.y - x2.y*sn.y);
        Qs[r][c4+2]  = elu1(x1.z*cs.z - x2.z*sn.z);
        Qs[r][c4+3]  = elu1(x1.w*cs.w - x2.w*sn.w);
        Qs[r][c4+32] = elu1(x1.x*sn.x + x2.x*cs.x);
        Qs[r][c4+33] = elu1(x1.y*sn.y + x2.y*cs.y);
        Qs[r][c4+34] = elu1(x1.z*sn.z + x2.z*cs.z);
        Qs[r][c4+35] = elu1(x1.w*sn.w + x2.w*cs.w);
    }
    __syncthreads();

    if (tid < 64) {
        float dsum = 0.f;
        #pragma unroll
        for (int d = 0; d < 64; ++d) dsum += Qs[tid][d] * ks[d];
        zs[tid] = 1.f / (dsum + 1e-6f);
    }
    __syncthreads();

    const int tx = tid & 15;
    const int ty = tid >> 4;
    float acc[4][4];
    #pragma unroll
    for (int i = 0; i < 4; ++i)
        #pragma unroll
        for (int j = 0; j < 4; ++j) acc[i][j] = 0.f;

    #pragma unroll
    for (int d = 0; d < 64; ++d) {
        float4 cv = *(const float4*)&Cs[d][tx*4];
        float q0 = Qs[ty*4+0][d];
        float q1 = Qs[ty*4+1][d];
        float q2 = Qs[ty*4+2][d];
        float q3 = Qs[ty*4+3][d];
        acc[0][0] = fmaf(q0, cv.x, acc[0][0]); acc[0][1] = fmaf(q0, cv.y, acc[0][1]);
        acc[0][2] = fmaf(q0, cv.z, acc[0][2]); acc[0][3] = fmaf(q0, cv.w, acc[0][3]);
        acc[1][0] = fmaf(q1, cv.x, acc[1][0]); acc[1][1] = fmaf(q1, cv.y, acc[1][1]);
        acc[1][2] = fmaf(q1, cv.z, acc[1][2]); acc[1][3] = fmaf(q1, cv.w, acc[1][3]);
        acc[2][0] = fmaf(q2, cv.x, acc[2][0]); acc[2][1] = fmaf(q2, cv.y, acc[2][1]);
        acc[2][2] = fmaf(q2, cv.z, acc[2][2]); acc[2][3] = fmaf(q2, cv.w, acc[2][3]);
        acc[3][0] = fmaf(q3, cv.x, acc[3][0]); acc[3][1] = fmaf(q3, cv.y, acc[3][1]);
        acc[3][2] = fmaf(q3, cv.z, acc[3][2]); acc[3][3] = fmaf(q3, cv.w, acc[3][3]);
    }

    #pragma unroll
    for (int i = 0; i < 4; ++i) {
        int r = ty*4 + i;
        float z = zs[r];
        float v0 = acc[i][0]*z, v1 = acc[i][1]*z, v2 = acc[i][2]*z, v3 = acc[i][3]*z;
        size_t off = (size_t)(r0 + r) * DM + h * HD + tx*4;
        __nv_bfloat16 h0 = __float2bfloat16_rn(v0), h1 = __float2bfloat16_rn(v1);
        __nv_bfloat16 h2 = __float2bfloat16_rn(v2), h3 = __float2bfloat16_rn(v3);
        *(uint32_t*)(g_AtH + off)     = pack_bf2(h0, h1);
        *(uint32_t*)(g_AtH + off + 2) = pack_bf2(h2, h3);
        *(uint32_t*)(g_AtL + off) = pack_bf2(
            __float2bfloat16_rn(v0 - __bfloat162float(h0)),
            __float2bfloat16_rn(v1 - __bfloat162float(h1)));
        *(uint32_t*)(g_AtL + off + 2) = pack_bf2(
            __float2bfloat16_rn(v2 - __bfloat162float(h2)),
            __float2bfloat16_rn(v3 - __bfloat162float(h3)));
    }
}

// ---------------------------------------------------------------------------
extern "C" void kernel_launch(void* const* d_in, const int* in_sizes, int n_in,
                              void* d_out, int out_size)
{
    const float* x  = (const float*)d_in[0];
    const float* Wq = (const float*)d_in[1];
    const float* bq = (const float*)d_in[2];
    const float* Wd = (const float*)d_in[3];
    const float* bd = (const float*)d_in[4];
    const float* Wu = (const float*)d_in[5];
    const float* bu = (const float*)d_in[6];
    const float* Wo = (const float*)d_in[7];
    const float* bo = (const float*)d_in[8];
    float* out = (float*)d_out;

    float *pQ, *pKV, *pCtx, *pKsum;
    __nv_bfloat16 *pXh, *pXl, *pCh, *pCl, *pAh, *pAl;
    __nv_bfloat16 *pWqH, *pWqL, *pWdH, *pWdL, *pWuH, *pWuL, *pWoH, *pWoL;
    cudaGetSymbolAddress((void**)&pQ,    g_Q);
    cudaGetSymbolAddress((void**)&pKV,   g_KV);
    cudaGetSymbolAddress((void**)&pCtx,  g_Ctx);
    cudaGetSymbolAddress((void**)&pKsum, g_Ksum);
    cudaGetSymbolAddress((void**)&pXh,   g_Xhi);
    cudaGetSymbolAddress((void**)&pXl,   g_Xlo);
    cudaGetSymbolAddress((void**)&pCh,   g_Chi);
    cudaGetSymbolAddress((void**)&pCl,   g_Clo);
    cudaGetSymbolAddress((void**)&pAh,   g_AtH);
    cudaGetSymbolAddress((void**)&pAl,   g_AtL);
    cudaGetSymbolAddress((void**)&pWqH,  g_WqH);
    cudaGetSymbolAddress((void**)&pWqL,  g_WqL);
    cudaGetSymbolAddress((void**)&pWdH,  g_WdH);
    cudaGetSymbolAddress((void**)&pWdL,  g_WdL);
    cudaGetSymbolAddress((void**)&pWuH,  g_WuH);
    cudaGetSymbolAddress((void**)&pWuL,  g_WuL);
    cudaGetSymbolAddress((void**)&pWoH,  g_WoH);
    cudaGetSymbolAddress((void**)&pWoL,  g_WoL);

    // weights: transpose + split
    split_weightT<<<dim3(512/32, 512/32), 256>>>(Wq, pWqH, pWqL, 512, 512);
    split_weightT<<<dim3(128/32, 512/32), 256>>>(Wd, pWdH, pWdL, 512, 128);
    split_weightT<<<dim3(1024/32, 128/32), 256>>>(Wu, pWuH, pWuL, 128, 1024);
    split_weightT<<<dim3(512/32, 512/32), 256>>>(Wo, pWoH, pWoL, 512, 512);
    // rope table
    rope_table<<<T_*32/128, 128>>>();
    // x split
    split_rows<<<(size_t)BT*512/4/256, 256>>>(x, pXh, pXl);

    // Q = x @ Wq + bq  (fp32 out)
    bgemm3<<<dim3(4, BT/128), 256>>>(pXh, pXl, pWqH, pWqL, bq,
                                     pQ, nullptr, nullptr, 512, 512);
    // C = x @ Wd + bd  (bf16 hi/lo out)
    bgemm3<<<dim3(1, BT/128), 256>>>(pXh, pXl, pWdH, pWdL, bd,
                                     nullptr, pCh, pCl, 128, 512);
    // KV = C @ Wu + bu (fp32 out)
    bgemm3<<<dim3(8, BT/128), 256>>>(pCh, pCl, pWuH, pWuL, bu,
                                     pKV, nullptr, nullptr, 1024, 128);

    // context (rope+elu on K fused into load)
    cudaMemsetAsync(pCtx,  0, sizeof(float) * B_*NH*HD*HD);
    cudaMemsetAsync(pKsum, 0, sizeof(float) * B_*NH*HD);
    context_kernel<<<dim3(T_/256, B_*NH), 256>>>();

    // attn (rope+elu on Q fused; writes bf16 hi/lo)
    attn_kernel<<<dim3(BT/64, NH), 256>>>();

    // out = Attn @ Wo + bo (fp32 out)
    bgemm3<<<dim3(4, BT/128), 256>>>(pAh, pAl, pWoH, pWoL, bo,
                                     out, nullptr, nullptr, 512, 512);
}